// round 1
// baseline (speedup 1.0000x reference)
#include <cuda_runtime.h>
#include <cstdint>

#define NB 16
#define CC 512
#define CPD 64
#define NN 4096

// scratch (static __device__ — no allocation)
__device__ float g_Q[(size_t)NB * CPD * NN];
__device__ float g_K[(size_t)NB * CPD * NN];
__device__ float g_V[(size_t)NB * CPD * NN];
__device__ float g_P[NB * 8 * CPD * CPD];   // energy partials per N-slice
__device__ float g_A[NB * CPD * CPD];       // attention
__device__ float g_M[NB * CC * CPD];        // M = Wo @ A

__device__ __forceinline__ uint32_t f2tf(float x) {
    uint32_t r;
    asm("cvt.rna.tf32.f32 %0, %1;" : "=r"(r) : "f"(x));
    return r;
}

__device__ __forceinline__ void mma8(float c[4], const uint32_t a[4], const uint32_t b[2]) {
    asm volatile(
        "mma.sync.aligned.m16n8k8.row.col.f32.tf32.tf32.f32 "
        "{%0,%1,%2,%3},{%4,%5,%6,%7},{%8,%9},{%0,%1,%2,%3};"
        : "+f"(c[0]), "+f"(c[1]), "+f"(c[2]), "+f"(c[3])
        : "r"(a[0]), "r"(a[1]), "r"(a[2]), "r"(a[3]), "r"(b[0]), "r"(b[1]));
}

// ============================================================================
// K1: QKV projection. out(64,4096) = W(64,512) @ X(512,4096) + bias
// grid (32 n-tiles, 3 proj, 16 batch), 256 threads, tile 64x128, BK=32
// ============================================================================
#define LDA1 36
#define LDB1 132

__global__ __launch_bounds__(256) void qkv_kernel(
    const float* __restrict__ x,
    const float* __restrict__ wq, const float* __restrict__ bq,
    const float* __restrict__ wk, const float* __restrict__ bk,
    const float* __restrict__ wv, const float* __restrict__ bv)
{
    extern __shared__ uint32_t sm1[];
    uint32_t* As = sm1;                  // [2][64][LDA1]
    uint32_t* Bs = sm1 + 2 * 64 * LDA1;  // [2][32][LDB1]

    const int b = blockIdx.z, proj = blockIdx.y;
    const int n0 = blockIdx.x * 128;
    const float* W    = proj == 0 ? wq : (proj == 1 ? wk : wv);
    const float* bias = proj == 0 ? bq : (proj == 1 ? bk : bv);
    float* out = proj == 0 ? g_Q : (proj == 1 ? g_K : g_V);
    const float* Xb = x + (size_t)b * CC * NN;

    const int tid = threadIdx.x;
    const int lane = tid & 31, warp = tid >> 5;
    const int wm = (warp & 1) * 32;
    const int wn = (warp >> 1) * 32;
    const int gid = lane >> 2, tig = lane & 3;

    float acc[2][4][4];
#pragma unroll
    for (int i = 0; i < 2; i++)
#pragma unroll
        for (int j = 0; j < 4; j++)
#pragma unroll
            for (int q = 0; q < 4; q++) acc[i][j][q] = 0.f;

    float4 pa[2], pb[4];

    // prologue: stage k-tile 0 into buffer 0
    {
#pragma unroll
        for (int i = 0; i < 2; i++) {
            int v = tid + i * 256, m = v >> 3, kv = v & 7;
            pa[i] = *reinterpret_cast<const float4*>(W + m * CC + kv * 4);
        }
#pragma unroll
        for (int i = 0; i < 4; i++) {
            int v = tid + i * 256, k = v >> 5, nv = v & 31;
            pb[i] = *reinterpret_cast<const float4*>(Xb + (size_t)k * NN + n0 + nv * 4);
        }
#pragma unroll
        for (int i = 0; i < 2; i++) {
            int v = tid + i * 256, m = v >> 3, kv = v & 7;
            uint32_t* d = As + m * LDA1 + kv * 4;
            d[0] = f2tf(pa[i].x); d[1] = f2tf(pa[i].y);
            d[2] = f2tf(pa[i].z); d[3] = f2tf(pa[i].w);
        }
#pragma unroll
        for (int i = 0; i < 4; i++) {
            int v = tid + i * 256, k = v >> 5, nv = v & 31;
            uint32_t* d = Bs + k * LDB1 + nv * 4;
            d[0] = f2tf(pb[i].x); d[1] = f2tf(pb[i].y);
            d[2] = f2tf(pb[i].z); d[3] = f2tf(pb[i].w);
        }
        __syncthreads();
    }

    for (int kt = 0; kt < 16; kt++) {
        const int buf = kt & 1;
        if (kt < 15) {
            const int k0 = (kt + 1) * 32;
#pragma unroll
            for (int i = 0; i < 2; i++) {
                int v = tid + i * 256, m = v >> 3, kv = v & 7;
                pa[i] = *reinterpret_cast<const float4*>(W + m * CC + k0 + kv * 4);
            }
#pragma unroll
            for (int i = 0; i < 4; i++) {
                int v = tid + i * 256, k = v >> 5, nv = v & 31;
                pb[i] = *reinterpret_cast<const float4*>(Xb + (size_t)(k0 + k) * NN + n0 + nv * 4);
            }
        }
        const uint32_t* Ab = As + buf * 64 * LDA1;
        const uint32_t* Bb = Bs + buf * 32 * LDB1;
#pragma unroll
        for (int kk = 0; kk < 4; kk++) {
            uint32_t af[2][4], bf[4][2];
#pragma unroll
            for (int mi = 0; mi < 2; mi++) {
                const uint32_t* ap = Ab + (wm + mi * 16 + gid) * LDA1 + kk * 8 + tig;
                af[mi][0] = ap[0];
                af[mi][1] = ap[8 * LDA1];
                af[mi][2] = ap[4];
                af[mi][3] = ap[8 * LDA1 + 4];
            }
#pragma unroll
            for (int ni = 0; ni < 4; ni++) {
                const uint32_t* bp = Bb + (kk * 8 + tig) * LDB1 + wn + ni * 8 + gid;
                bf[ni][0] = bp[0];
                bf[ni][1] = bp[4 * LDB1];
            }
#pragma unroll
            for (int mi = 0; mi < 2; mi++)
#pragma unroll
                for (int ni = 0; ni < 4; ni++) mma8(acc[mi][ni], af[mi], bf[ni]);
        }
        if (kt < 15) {
            uint32_t* Ad = As + (buf ^ 1) * 64 * LDA1;
            uint32_t* Bd = Bs + (buf ^ 1) * 32 * LDB1;
#pragma unroll
            for (int i = 0; i < 2; i++) {
                int v = tid + i * 256, m = v >> 3, kv = v & 7;
                uint32_t* d = Ad + m * LDA1 + kv * 4;
                d[0] = f2tf(pa[i].x); d[1] = f2tf(pa[i].y);
                d[2] = f2tf(pa[i].z); d[3] = f2tf(pa[i].w);
            }
#pragma unroll
            for (int i = 0; i < 4; i++) {
                int v = tid + i * 256, k = v >> 5, nv = v & 31;
                uint32_t* d = Bd + k * LDB1 + nv * 4;
                d[0] = f2tf(pb[i].x); d[1] = f2tf(pb[i].y);
                d[2] = f2tf(pb[i].z); d[3] = f2tf(pb[i].w);
            }
            __syncthreads();
        }
    }

    // epilogue: + bias, fp32 stores
#pragma unroll
    for (int mi = 0; mi < 2; mi++) {
        int r0 = wm + mi * 16 + gid;
        float b0v = bias[r0], b1v = bias[r0 + 8];
#pragma unroll
        for (int ni = 0; ni < 4; ni++) {
            int cc = n0 + wn + ni * 8 + 2 * tig;
            float2 v0 = make_float2(acc[mi][ni][0] + b0v, acc[mi][ni][1] + b0v);
            float2 v1 = make_float2(acc[mi][ni][2] + b1v, acc[mi][ni][3] + b1v);
            *reinterpret_cast<float2*>(out + ((size_t)b * CPD + r0) * NN + cc) = v0;
            *reinterpret_cast<float2*>(out + ((size_t)b * CPD + r0 + 8) * NN + cc) = v1;
        }
    }
}

// ============================================================================
// K2: energy partials. E_part(64,64) = K[:, s*512:(s+1)*512] @ Q[...]^T
// grid (8 slices, 16 batch), 128 threads (4 warps, 2x2 warp grid)
// ============================================================================
#define LD2 36

__global__ __launch_bounds__(128) void energy_kernel()
{
    __shared__ uint32_t Ks[2][64][LD2];
    __shared__ uint32_t Qs[2][64][LD2];
    const int s = blockIdx.x, b = blockIdx.y;
    const int nbase = s * 512;
    const float* Kb = g_K + (size_t)b * CPD * NN + nbase;
    const float* Qb = g_Q + (size_t)b * CPD * NN + nbase;

    const int tid = threadIdx.x, lane = tid & 31, warp = tid >> 5;
    const int wm = (warp & 1) * 32, wn = (warp >> 1) * 32;
    const int gid = lane >> 2, tig = lane & 3;

    float acc[2][4][4];
#pragma unroll
    for (int i = 0; i < 2; i++)
#pragma unroll
        for (int j = 0; j < 4; j++)
#pragma unroll
            for (int q = 0; q < 4; q++) acc[i][j][q] = 0.f;

    float4 pk[4], pq[4];
    // prologue: stage k-tile 0 (64x32 each)
    {
#pragma unroll
        for (int i = 0; i < 4; i++) {
            int v = tid + i * 128, r = v >> 3, kv = v & 7;
            pk[i] = *reinterpret_cast<const float4*>(Kb + (size_t)r * NN + kv * 4);
            pq[i] = *reinterpret_cast<const float4*>(Qb + (size_t)r * NN + kv * 4);
        }
#pragma unroll
        for (int i = 0; i < 4; i++) {
            int v = tid + i * 128, r = v >> 3, kv = v & 7;
            uint32_t* dk = &Ks[0][r][kv * 4];
            dk[0] = f2tf(pk[i].x); dk[1] = f2tf(pk[i].y);
            dk[2] = f2tf(pk[i].z); dk[3] = f2tf(pk[i].w);
            uint32_t* dq = &Qs[0][r][kv * 4];
            dq[0] = f2tf(pq[i].x); dq[1] = f2tf(pq[i].y);
            dq[2] = f2tf(pq[i].z); dq[3] = f2tf(pq[i].w);
        }
        __syncthreads();
    }

    for (int kt = 0; kt < 16; kt++) {
        const int buf = kt & 1;
        if (kt < 15) {
            const int k0 = (kt + 1) * 32;
#pragma unroll
            for (int i = 0; i < 4; i++) {
                int v = tid + i * 128, r = v >> 3, kv = v & 7;
                pk[i] = *reinterpret_cast<const float4*>(Kb + (size_t)r * NN + k0 + kv * 4);
                pq[i] = *reinterpret_cast<const float4*>(Qb + (size_t)r * NN + k0 + kv * 4);
            }
        }
#pragma unroll
        for (int kk = 0; kk < 4; kk++) {
            uint32_t af[2][4], bf[4][2];
#pragma unroll
            for (int mi = 0; mi < 2; mi++) {
                const uint32_t* ap = &Ks[buf][wm + mi * 16 + gid][kk * 8 + tig];
                af[mi][0] = ap[0];
                af[mi][1] = ap[8 * LD2];
                af[mi][2] = ap[4];
                af[mi][3] = ap[8 * LD2 + 4];
            }
#pragma unroll
            for (int ni = 0; ni < 4; ni++) {
                const uint32_t* bp = &Qs[buf][wn + ni * 8 + gid][kk * 8 + tig];
                bf[ni][0] = bp[0];
                bf[ni][1] = bp[4];
            }
#pragma unroll
            for (int mi = 0; mi < 2; mi++)
#pragma unroll
                for (int ni = 0; ni < 4; ni++) mma8(acc[mi][ni], af[mi], bf[ni]);
        }
        if (kt < 15) {
            const int nbuf = buf ^ 1;
#pragma unroll
            for (int i = 0; i < 4; i++) {
                int v = tid + i * 128, r = v >> 3, kv = v & 7;
                uint32_t* dk = &Ks[nbuf][r][kv * 4];
                dk[0] = f2tf(pk[i].x); dk[1] = f2tf(pk[i].y);
                dk[2] = f2tf(pk[i].z); dk[3] = f2tf(pk[i].w);
                uint32_t* dq = &Qs[nbuf][r][kv * 4];
                dq[0] = f2tf(pq[i].x); dq[1] = f2tf(pq[i].y);
                dq[2] = f2tf(pq[i].z); dq[3] = f2tf(pq[i].w);
            }
            __syncthreads();
        }
    }

    float* P = g_P + ((size_t)(b * 8 + s) * CPD) * CPD;
#pragma unroll
    for (int mi = 0; mi < 2; mi++) {
        int r0 = wm + mi * 16 + gid;
#pragma unroll
        for (int ni = 0; ni < 4; ni++) {
            int cc = wn + ni * 8 + 2 * tig;
            *reinterpret_cast<float2*>(P + (size_t)r0 * CPD + cc) =
                make_float2(acc[mi][ni][0], acc[mi][ni][1]);
            *reinterpret_cast<float2*>(P + (size_t)(r0 + 8) * CPD + cc) =
                make_float2(acc[mi][ni][2], acc[mi][ni][3]);
        }
    }
}

// ============================================================================
// K3: reduce partials + row softmax. grid 16, 128 threads
// ============================================================================
__global__ __launch_bounds__(128) void softmax_kernel()
{
    __shared__ float Es[64][65];
    const int b = blockIdx.x, tid = threadIdx.x;
    for (int idx = tid; idx < 4096; idx += 128) {
        float ssum = 0.f;
#pragma unroll
        for (int p = 0; p < 8; p++) ssum += g_P[(size_t)(b * 8 + p) * 4096 + idx];
        Es[idx >> 6][idx & 63] = ssum;
    }
    __syncthreads();
    if (tid < 64) {
        float m = -1e30f;
#pragma unroll
        for (int j = 0; j < 64; j++) m = fmaxf(m, Es[tid][j]);
        float ssum = 0.f;
#pragma unroll
        for (int j = 0; j < 64; j++) {
            float e = __expf(Es[tid][j] - m);
            Es[tid][j] = e;
            ssum += e;
        }
        float inv = 1.f / ssum;
#pragma unroll
        for (int j = 0; j < 64; j++)
            g_A[((size_t)b * CPD + tid) * CPD + j] = Es[tid][j] * inv;
    }
}

// ============================================================================
// K4: M = Wo @ A (512x64 = (512x64)@(64x64)) per batch. grid (8 c-tiles, 16 b)
// ============================================================================
__global__ __launch_bounds__(256) void momix_kernel(const float* __restrict__ wo)
{
    __shared__ float Wos[64][65];
    __shared__ float Aas[64][64];
    const int c0 = blockIdx.x * 64, b = blockIdx.y, tid = threadIdx.x;

#pragma unroll
    for (int i = 0; i < 4; i++) {
        int v = tid + i * 256, m = v >> 4, kv = v & 15;
        float4 t = *reinterpret_cast<const float4*>(wo + (size_t)(c0 + m) * CPD + kv * 4);
        Wos[m][kv * 4 + 0] = t.x; Wos[m][kv * 4 + 1] = t.y;
        Wos[m][kv * 4 + 2] = t.z; Wos[m][kv * 4 + 3] = t.w;
        float4 a = *reinterpret_cast<const float4*>(g_A + ((size_t)b * CPD + m) * CPD + kv * 4);
        *reinterpret_cast<float4*>(&Aas[m][kv * 4]) = a;
    }
    __syncthreads();

    const int cl = tid >> 2, jg = tid & 3;
    float acc[16];
#pragma unroll
    for (int q = 0; q < 16; q++) acc[q] = 0.f;
    for (int o = 0; o < 64; o++) {
        float w = Wos[cl][o];
        const float4* ar = reinterpret_cast<const float4*>(&Aas[o][jg * 16]);
        float4 a0 = ar[0], a1 = ar[1], a2 = ar[2], a3 = ar[3];
        acc[0]  += w * a0.x; acc[1]  += w * a0.y; acc[2]  += w * a0.z; acc[3]  += w * a0.w;
        acc[4]  += w * a1.x; acc[5]  += w * a1.y; acc[6]  += w * a1.z; acc[7]  += w * a1.w;
        acc[8]  += w * a2.x; acc[9]  += w * a2.y; acc[10] += w * a2.z; acc[11] += w * a2.w;
        acc[12] += w * a3.x; acc[13] += w * a3.y; acc[14] += w * a3.z; acc[15] += w * a3.w;
    }
    float* dst = g_M + ((size_t)b * CC + c0 + cl) * CPD + jg * 16;
#pragma unroll
    for (int q = 0; q < 4; q++)
        *reinterpret_cast<float4*>(dst + q * 4) =
            make_float4(acc[q * 4 + 0], acc[q * 4 + 1], acc[q * 4 + 2], acc[q * 4 + 3]);
}

// ============================================================================
// K5: Y = gamma*(M @ V + bo) + X. tile 64x64, K=64 (single stage)
// grid (64 n-tiles, 8 c-tiles, 16 b), 128 threads
// ============================================================================
#define LD4 68

__global__ __launch_bounds__(128) void out_kernel(
    const float* __restrict__ x, const float* __restrict__ bo,
    const float* __restrict__ gamma, float* __restrict__ y)
{
    __shared__ uint32_t Ms[64][LD4];
    __shared__ uint32_t Vs[64][LD4];
    const int n0 = blockIdx.x * 64, c0 = blockIdx.y * 64, b = blockIdx.z;
    const int tid = threadIdx.x, lane = tid & 31, warp = tid >> 5;
    const int wm = (warp & 1) * 32, wn = (warp >> 1) * 32;
    const int gid = lane >> 2, tig = lane & 3;

#pragma unroll
    for (int i = 0; i < 8; i++) {
        int v = tid + i * 128, m = v >> 4, kv = v & 15;
        float4 t = *reinterpret_cast<const float4*>(g_M + ((size_t)b * CC + c0 + m) * CPD + kv * 4);
        uint32_t* d = &Ms[m][kv * 4];
        d[0] = f2tf(t.x); d[1] = f2tf(t.y); d[2] = f2tf(t.z); d[3] = f2tf(t.w);
        float4 u = *reinterpret_cast<const float4*>(g_V + ((size_t)b * CPD + m) * NN + n0 + kv * 4);
        uint32_t* e = &Vs[m][kv * 4];
        e[0] = f2tf(u.x); e[1] = f2tf(u.y); e[2] = f2tf(u.z); e[3] = f2tf(u.w);
    }
    __syncthreads();

    float acc[2][4][4];
#pragma unroll
    for (int i = 0; i < 2; i++)
#pragma unroll
        for (int j = 0; j < 4; j++)
#pragma unroll
            for (int q = 0; q < 4; q++) acc[i][j][q] = 0.f;

#pragma unroll
    for (int kk = 0; kk < 8; kk++) {
        uint32_t af[2][4], bf[4][2];
#pragma unroll
        for (int mi = 0; mi < 2; mi++) {
            const uint32_t* ap = &Ms[wm + mi * 16 + gid][kk * 8 + tig];
            af[mi][0] = ap[0];
            af[mi][1] = ap[8 * LD4];
            af[mi][2] = ap[4];
            af[mi][3] = ap[8 * LD4 + 4];
        }
#pragma unroll
        for (int ni = 0; ni < 4; ni++) {
            const uint32_t* bp = &Vs[kk * 8 + tig][wn + ni * 8 + gid];
            bf[ni][0] = bp[0];
            bf[ni][1] = bp[4 * LD4];
        }
#pragma unroll
        for (int mi = 0; mi < 2; mi++)
#pragma unroll
            for (int ni = 0; ni < 4; ni++) mma8(acc[mi][ni], af[mi], bf[ni]);
    }

    const float g = gamma[0];
#pragma unroll
    for (int mi = 0; mi < 2; mi++) {
        int r0 = wm + mi * 16 + gid;
        int ch0 = c0 + r0, ch1 = c0 + r0 + 8;
        float bo0 = bo[ch0], bo1 = bo[ch1];
#pragma unroll
        for (int ni = 0; ni < 4; ni++) {
            int nn = n0 + wn + ni * 8 + 2 * tig;
            size_t off0 = ((size_t)b * CC + ch0) * NN + nn;
            size_t off1 = ((size_t)b * CC + ch1) * NN + nn;
            float2 x0 = *reinterpret_cast<const float2*>(x + off0);
            float2 x1 = *reinterpret_cast<const float2*>(x + off1);
            float2 o0, o1;
            o0.x = g * (acc[mi][ni][0] + bo0) + x0.x;
            o0.y = g * (acc[mi][ni][1] + bo0) + x0.y;
            o1.x = g * (acc[mi][ni][2] + bo1) + x1.x;
            o1.y = g * (acc[mi][ni][3] + bo1) + x1.y;
            *reinterpret_cast<float2*>(y + off0) = o0;
            *reinterpret_cast<float2*>(y + off1) = o1;
        }
    }
}

// ============================================================================
extern "C" void kernel_launch(void* const* d_in, const int* in_sizes, int n_in,
                              void* d_out, int out_size)
{
    const float* x  = (const float*)d_in[0];
    const float* wq = (const float*)d_in[1];
    const float* bq = (const float*)d_in[2];
    const float* wk = (const float*)d_in[3];
    const float* bk = (const float*)d_in[4];
    const float* wv = (const float*)d_in[5];
    const float* bv = (const float*)d_in[6];
    const float* wo = (const float*)d_in[7];
    const float* bo = (const float*)d_in[8];
    const float* gm = (const float*)d_in[9];
    float* y = (float*)d_out;

    cudaFuncSetAttribute(qkv_kernel, cudaFuncAttributeMaxDynamicSharedMemorySize, 52224);

    qkv_kernel<<<dim3(32, 3, 16), 256, 52224>>>(x, wq, bq, wk, bk, wv, bv);
    energy_kernel<<<dim3(8, 16), 128>>>();
    softmax_kernel<<<16, 128>>>();
    momix_kernel<<<dim3(8, 16), 256>>>(wo);
    out_kernel<<<dim3(64, 8, 16), 128>>>(x, bo, gm, y);
}